// round 15
// baseline (speedup 1.0000x reference)
#include <cuda_runtime.h>
#include <cuda_fp16.h>
#include <cstdint>

#define L  384
#define D  128
#define H  128
#define LL (L * L)   // 147456

// Scratch — static device globals (no cudaMalloc allowed).
__device__ __half g_LhT[(size_t)H * LL];  // [h][i*L+k]  (fp16)
__device__ __half g_RhT[(size_t)H * LL];  // [h][j*L+k]  (fp16, j-major)
__device__ __half g_updT[(size_t)H * LL]; // [h][i*L+j]  (fp16)
__device__ __half g_Wo2h[D * H];          // [d][h] = fp16(W_out[d][h])

// ---------------------------------------------------------------------------
// helpers
// ---------------------------------------------------------------------------
__device__ __forceinline__ void mma16(float c[4], const unsigned a[4], const unsigned b[2]) {
    asm volatile(
        "mma.sync.aligned.m16n8k16.row.col.f32.f16.f16.f32 "
        "{%0,%1,%2,%3}, {%4,%5,%6,%7}, {%8,%9}, {%0,%1,%2,%3};"
        : "+f"(c[0]), "+f"(c[1]), "+f"(c[2]), "+f"(c[3])
        : "r"(a[0]), "r"(a[1]), "r"(a[2]), "r"(a[3]), "r"(b[0]), "r"(b[1]));
}

__device__ __forceinline__ void ldsm4h(unsigned r[4], const __half* p) {
    unsigned a = (unsigned)__cvta_generic_to_shared(p);
    asm volatile("ldmatrix.sync.aligned.m8n8.x4.shared.b16 {%0,%1,%2,%3}, [%4];"
                 : "=r"(r[0]), "=r"(r[1]), "=r"(r[2]), "=r"(r[3]) : "r"(a));
}
__device__ __forceinline__ void ldsm4t(unsigned r[4], const __half* p) {
    unsigned a = (unsigned)__cvta_generic_to_shared(p);
    asm volatile("ldmatrix.sync.aligned.m8n8.x4.trans.shared.b16 {%0,%1,%2,%3}, [%4];"
                 : "=r"(r[0]), "=r"(r[1]), "=r"(r[2]), "=r"(r[3]) : "r"(a));
}

__device__ __forceinline__ void cpa16(void* dst, const void* src) {
    unsigned sa = (unsigned)__cvta_generic_to_shared(dst);
    asm volatile("cp.async.cg.shared.global [%0], [%1], 16;" :: "r"(sa), "l"(src));
}
__device__ __forceinline__ void cpa_commit() { asm volatile("cp.async.commit_group;"); }
__device__ __forceinline__ void cpa_wait0()  { asm volatile("cp.async.wait_group 0;"); }
__device__ __forceinline__ void cpa_wait1()  { asm volatile("cp.async.wait_group 1;"); }

// ---------------------------------------------------------------------------
// Kernel 0: fp16-round W_out (native [d][h] order) -> g_Wo2h
// ---------------------------------------------------------------------------
__global__ __launch_bounds__(256) void k_wt(const float* __restrict__ Wo) {
    int idx = blockIdx.x * 256 + threadIdx.x;   // 16384
    g_Wo2h[idx] = __float2half_rn(Wo[idx]);
}

// ---------------------------------------------------------------------------
// Kernel 1: projection GEMM — fp16 mma + ldmatrix (round-12, committed).
// ---------------------------------------------------------------------------
#define PCS(n, m) smf[(n) * 132 + (m)]

__global__ __launch_bounds__(256) void k_proj(
    const float* __restrict__ P, const float* __restrict__ mask,
    const float* __restrict__ Wl, const float* __restrict__ Wr)
{
    __shared__ __align__(16) float smf[5120];   // 20,480 B (halves alias floats)
    __half* sm = (__half*)smf;
    float* mV = smf + 32 * 132 + 16;            // 128 mask vals (epilogue reuse)

    const int tid = threadIdx.x;
    const int wid = tid >> 5, lane = tid & 31;
    const int wm = wid & 3, wn = wid >> 2;
    const int group = lane >> 2, tid4 = lane & 3;
    const int bid = blockIdx.x;
    const bool isL = (blockIdx.y == 0);
    const float* __restrict__ W = isL ? Wl : Wr;

    int srcBase, srcStride, dmBase;
    if (isL) {
        srcBase = bid * 128;  srcStride = 1;  dmBase = bid * 128;
    } else {
        int j = bid / 3, k0p = (bid % 3) * 128;
        srcBase = k0p * L + j;  srcStride = L;  dmBase = j * L + k0p;
    }

    int aOff[2], bOff[4];
#pragma unroll
    for (int mt = 0; mt < 2; mt++)
        aOff[mt] = (wm * 32 + mt * 16 + (lane & 7) + 8 * ((lane >> 3) & 1)) * 40
                 + 8 * (lane >> 4);
#pragma unroll
    for (int p = 0; p < 4; p++)
        bOff[p] = 5120 + (wn * 64 + p * 16 + (lane & 7) + 8 * (lane >> 4)) * 40
                + 8 * ((lane >> 3) & 1);

    float acc[2][8][4];
#pragma unroll
    for (int mt = 0; mt < 2; mt++)
#pragma unroll
        for (int nt = 0; nt < 8; nt++)
#pragma unroll
            for (int v = 0; v < 4; v++) acc[mt][nt][v] = 0.f;

    const int mld = tid >> 3;          // 0..31 (+32p)
    const int kld = (tid & 7) * 4;     // 0..28

    float4 va[4], vb[4];
#define P_FETCH(k0)                                                                 \
    {                                                                               \
        _Pragma("unroll")                                                           \
        for (int p = 0; p < 4; p++) {                                               \
            int m = mld + p * 32;                                                   \
            va[p] = *(const float4*)&P[(size_t)(srcBase + (size_t)m * srcStride) * D + (k0) + kld]; \
            vb[p] = *(const float4*)&W[m * D + (k0) + kld];                         \
        }                                                                           \
    }
#define P_STORE()                                                                   \
    {                                                                               \
        _Pragma("unroll")                                                           \
        for (int p = 0; p < 4; p++) {                                               \
            int m = mld + p * 32;                                                   \
            __half2 a0 = __floats2half2_rn(va[p].x, va[p].y);                       \
            __half2 a1 = __floats2half2_rn(va[p].z, va[p].w);                       \
            __half2 b0 = __floats2half2_rn(vb[p].x, vb[p].y);                       \
            __half2 b1 = __floats2half2_rn(vb[p].z, vb[p].w);                       \
            *(unsigned*)&sm[m * 40 + kld]            = *(unsigned*)&a0;             \
            *(unsigned*)&sm[m * 40 + kld + 2]        = *(unsigned*)&a1;             \
            *(unsigned*)&sm[5120 + m * 40 + kld]     = *(unsigned*)&b0;             \
            *(unsigned*)&sm[5120 + m * 40 + kld + 2] = *(unsigned*)&b1;             \
        }                                                                           \
    }

    P_FETCH(0);

#pragma unroll 1
    for (int it = 0; it < 4; it++) {
        __syncthreads();
        P_STORE();
        __syncthreads();
        if (it < 3) P_FETCH((it + 1) * 32);
#pragma unroll
        for (int ks = 0; ks < 2; ks++) {
            const int k = ks * 16;
            unsigned a[2][4], b[4][4];
#pragma unroll
            for (int mt = 0; mt < 2; mt++)
                ldsm4h(a[mt], &sm[aOff[mt] + k]);
#pragma unroll
            for (int p = 0; p < 4; p++)
                ldsm4h(b[p], &sm[bOff[p] + k]);
#pragma unroll
            for (int mt = 0; mt < 2; mt++)
#pragma unroll
                for (int p = 0; p < 4; p++) {
                    mma16(acc[mt][2 * p],     a[mt], &b[p][0]);
                    mma16(acc[mt][2 * p + 1], a[mt], &b[p][2]);
                }
        }
    }
#undef P_FETCH
#undef P_STORE

    __syncthreads();
    if (tid < 128) mV[tid] = mask[dmBase + tid];
    __half* __restrict__ dst = isL ? g_LhT : g_RhT;

#pragma unroll 1
    for (int nc = 0; nc < 4; nc++) {
        __syncthreads();
        if (wn == (nc >> 1)) {
#pragma unroll
            for (int nt2 = 0; nt2 < 4; nt2++) {
                int nt = (nc & 1) * 4 + nt2;
                int cc = nt2 * 8 + 2 * tid4;
#pragma unroll
                for (int mt = 0; mt < 2; mt++) {
                    int r = wm * 32 + mt * 16 + group;
                    PCS(cc,     r)     = acc[mt][nt][0];
                    PCS(cc + 1, r)     = acc[mt][nt][1];
                    PCS(cc,     r + 8) = acc[mt][nt][2];
                    PCS(cc + 1, r + 8) = acc[mt][nt][3];
                }
            }
        }
        __syncthreads();
#pragma unroll
        for (int p = 0; p < 4; p++) {
            int nr = (tid >> 5) + p * 8;
            int m  = (tid & 31) * 4;
            __half2 h0 = __floats2half2_rn(PCS(nr, m + 0) * mV[m + 0],
                                           PCS(nr, m + 1) * mV[m + 1]);
            __half2 h1 = __floats2half2_rn(PCS(nr, m + 2) * mV[m + 2],
                                           PCS(nr, m + 3) * mV[m + 3]);
            uint2 u = make_uint2(*(unsigned*)&h0, *(unsigned*)&h1);
            *(uint2*)&dst[(size_t)(nc * 32 + nr) * LL + dmBase + m] = u;
        }
    }
#undef PCS
}

// ---------------------------------------------------------------------------
// Kernel 2: triangle einsum — fp16 mma + ldmatrix, BK=64, one-sync 2-stage
// (round-14, committed). Dynamic smem 73,728 B.
// ---------------------------------------------------------------------------
#define T_STG 18432                   // halves per stage: A 128*72 + B 128*72
#define T_SMEM (2 * T_STG * 2)        // 73,728 B
#define TCS(m, j)    smf[(m) * 132 + (j)]

__global__ __launch_bounds__(256, 2) void k_tri() {
    extern __shared__ __align__(16) float smf[];
    __half* sm = (__half*)smf;

    const int tid = threadIdx.x;
    const int wid = tid >> 5, lane = tid & 31;
    const int wm = wid & 3, wn = wid >> 2;
    const int group = lane >> 2, tid4 = lane & 3;
    const size_t hoff = (size_t)blockIdx.z * LL;
    const int i0 = blockIdx.y * 128;
    const int j0 = blockIdx.x * 128;

    const __half* __restrict__ A = g_LhT + hoff;
    const __half* __restrict__ B = g_RhT + hoff;

    int aOff[2], bOff[4];
#pragma unroll
    for (int mt = 0; mt < 2; mt++)
        aOff[mt] = (wm * 32 + mt * 16 + (lane & 7) + 8 * ((lane >> 3) & 1)) * 72
                 + 8 * (lane >> 4);
#pragma unroll
    for (int p = 0; p < 4; p++)
        bOff[p] = 9216 + (wn * 64 + p * 16 + (lane & 7) + 8 * (lane >> 4)) * 72
                + 8 * ((lane >> 3) & 1);

    float acc[2][8][4];
#pragma unroll
    for (int mt = 0; mt < 2; mt++)
#pragma unroll
        for (int nt = 0; nt < 8; nt++)
#pragma unroll
            for (int v = 0; v < 4; v++) acc[mt][nt][v] = 0.f;

#define T_LOAD(s, k0)                                                              \
    {                                                                              \
        _Pragma("unroll")                                                          \
        for (int p = 0; p < 4; p++) {                                              \
            int task = tid + p * 256;                                              \
            int r = task >> 3, q = task & 7;                                       \
            cpa16(&sm[(s) * T_STG + r * 72 + q * 8],                               \
                  &A[(size_t)(i0 + r) * L + (k0) + q * 8]);                        \
            cpa16(&sm[(s) * T_STG + 9216 + r * 72 + q * 8],                        \
                  &B[(size_t)(j0 + r) * L + (k0) + q * 8]);                        \
        }                                                                          \
    }

    T_LOAD(0, 0);  cpa_commit();

#pragma unroll 1
    for (int it = 0; it < 6; it++) {
        const int s = it & 1;
        cpa_wait0();
        __syncthreads();
        if (it < 5) T_LOAD(s ^ 1, (it + 1) * 64);
        cpa_commit();
#pragma unroll
        for (int ks = 0; ks < 4; ks++) {
            const int k = ks * 16;
            unsigned a[2][4], b[4][4];
#pragma unroll
            for (int mt = 0; mt < 2; mt++)
                ldsm4h(a[mt], &sm[s * T_STG + aOff[mt] + k]);
#pragma unroll
            for (int p = 0; p < 4; p++)
                ldsm4h(b[p], &sm[s * T_STG + bOff[p] + k]);
#pragma unroll
            for (int mt = 0; mt < 2; mt++)
#pragma unroll
                for (int p = 0; p < 4; p++) {
                    mma16(acc[mt][2 * p],     a[mt], &b[p][0]);
                    mma16(acc[mt][2 * p + 1], a[mt], &b[p][2]);
                }
        }
    }
#undef T_LOAD

    // Epilogue: two 64-row chunks staged through smem, coalesced fp16 store.
#pragma unroll 1
    for (int mc = 0; mc < 2; mc++) {
        __syncthreads();
        if ((wm >> 1) == mc) {
#pragma unroll
            for (int nt = 0; nt < 8; nt++) {
                int cc = wn * 64 + nt * 8 + 2 * tid4;
#pragma unroll
                for (int mt = 0; mt < 2; mt++) {
                    int r = (wm & 1) * 32 + mt * 16 + group;
                    TCS(r,     cc)     = acc[mt][nt][0];
                    TCS(r,     cc + 1) = acc[mt][nt][1];
                    TCS(r + 8, cc)     = acc[mt][nt][2];
                    TCS(r + 8, cc + 1) = acc[mt][nt][3];
                }
            }
        }
        __syncthreads();
#pragma unroll
        for (int p = 0; p < 8; p++) {
            int row = (tid >> 5) + p * 8;
            int j   = (tid & 31) * 4;
            __half2 h0 = __floats2half2_rn(TCS(row, j + 0), TCS(row, j + 1));
            __half2 h1 = __floats2half2_rn(TCS(row, j + 2), TCS(row, j + 3));
            uint2 u = make_uint2(*(unsigned*)&h0, *(unsigned*)&h1);
            *(uint2*)&g_updT[hoff + (size_t)(i0 + mc * 64 + row) * L + j0 + j] = u;
        }
    }
#undef TCS
}

// ---------------------------------------------------------------------------
// Kernel 3: output projection (fp16 mma) + residual + mask + LN.
// RESTRUCTURED: 256 threads, 8 warps, 32x32 warp tiles (2x4 grid) over the
// 64x128 CTA tile. acc halves to 32 regs -> __launch_bounds__(256,3) = 3
// CTAs/SM (24 warps). Single-pass LN epilogue (64 rows x 4 threads = 256).
// ---------------------------------------------------------------------------
#define F_STG 4224                    // halves per stage: A 16*72 + B 128*24
#define FCS(m, d)    sm[(m) * 132 + (d)]

__global__ __launch_bounds__(256, 3) void k_fin(
    const float* __restrict__ P, const float* __restrict__ mask,
    const float* __restrict__ gamma, const float* __restrict__ beta,
    float* __restrict__ out)
{
    __shared__ __align__(16) float sm[8448];   // 33,792 B (stages alias)
    __half* smh = (__half*)sm;

    const int tid = threadIdx.x;
    const int wid = tid >> 5, lane = tid & 31;
    const int wm = wid & 1, wn = wid >> 1;      // 2(m) x 4(n) warp grid
    const int group = lane >> 2, tid4 = lane & 3;
    const int pairBase = blockIdx.x * 64;

    int aOff[2], bOff[2];
#pragma unroll
    for (int mt = 0; mt < 2; mt++)
        aOff[mt] = ((lane & 7) + 8 * (lane >> 4)) * 72
                 + wm * 32 + mt * 16 + 8 * ((lane >> 3) & 1);
#pragma unroll
    for (int p = 0; p < 2; p++)
        bOff[p] = 1152 + (wn * 32 + p * 16 + (lane & 7) + 8 * (lane >> 4)) * 24
                + 8 * ((lane >> 3) & 1);

    float acc[2][4][4];
#pragma unroll
    for (int mt = 0; mt < 2; mt++)
#pragma unroll
        for (int nt = 0; nt < 4; nt++)
#pragma unroll
            for (int v = 0; v < 4; v++) acc[mt][nt][v] = 0.f;

#define F_LOAD(s, k0)                                                                \
    {                                                                                \
        if (tid < 128) {   /* A: 16 rows x 64 halves = 128 chunks */                 \
            int k = tid >> 3, m8 = (tid & 7) * 8;                                    \
            cpa16(&smh[(s) * F_STG + k * 72 + m8],                                   \
                  &g_updT[(size_t)((k0) + k) * LL + pairBase + m8]);                 \
        }                                                                            \
        {   /* B: 128 rows x 16 halves = 256 chunks, 1 per thread */                 \
            int n = tid >> 1, q = (tid & 1) * 8;                                     \
            cpa16(&smh[(s) * F_STG + 1152 + n * 24 + q],                             \
                  &g_Wo2h[n * H + (k0) + q]);                                        \
        }                                                                            \
    }

    F_LOAD(0, 0);  cpa_commit();
    F_LOAD(1, 16); cpa_commit();

#pragma unroll 1
    for (int it = 0; it < 8; it++) {
        const int s = it % 3;
        cpa_wait1();
        __syncthreads();
        if (it + 2 < 8) F_LOAD((it + 2) % 3, (it + 2) * 16);
        cpa_commit();
        unsigned a[2][4], b[2][4];
#pragma unroll
        for (int mt = 0; mt < 2; mt++)
            ldsm4t(a[mt], &smh[s * F_STG + aOff[mt]]);
#pragma unroll
        for (int p = 0; p < 2; p++)
            ldsm4h(b[p], &smh[s * F_STG + bOff[p]]);
#pragma unroll
        for (int mt = 0; mt < 2; mt++)
#pragma unroll
            for (int p = 0; p < 2; p++) {
                mma16(acc[mt][2 * p],     a[mt], &b[p][0]);
                mma16(acc[mt][2 * p + 1], a[mt], &b[p][2]);
            }
    }

    // Epilogue: stage 64x128 acc tile -> smem (each warp its 32x32 block).
    __syncthreads();
#pragma unroll
    for (int nt = 0; nt < 4; nt++) {
        int cc = wn * 32 + nt * 8 + 2 * tid4;
#pragma unroll
        for (int mt = 0; mt < 2; mt++) {
            int r = wm * 32 + mt * 16 + group;
            FCS(r,     cc)     = acc[mt][nt][0];
            FCS(r,     cc + 1) = acc[mt][nt][1];
            FCS(r + 8, cc)     = acc[mt][nt][2];
            FCS(r + 8, cc + 1) = acc[mt][nt][3];
        }
    }
    __syncthreads();

    // LayerNorm: single pass — 64 rows x 4 threads (32 d each).
    {
        const int row = tid >> 2;
        const int q   = tid & 3;
        const int pair = pairBase + row;
        const float mk = mask[pair];

        float pn[32];
        float s = 0.f, sq = 0.f;
#pragma unroll
        for (int u = 0; u < 8; u++) {
            float4 pv = *(const float4*)&P[(size_t)pair * D + q * 32 + 4 * u];
            pn[4 * u + 0] = pv.x + mk * FCS(row, q * 32 + 4 * u + 0);
            pn[4 * u + 1] = pv.y + mk * FCS(row, q * 32 + 4 * u + 1);
            pn[4 * u + 2] = pv.z + mk * FCS(row, q * 32 + 4 * u + 2);
            pn[4 * u + 3] = pv.w + mk * FCS(row, q * 32 + 4 * u + 3);
        }
#pragma unroll
        for (int v = 0; v < 32; v++) { s += pn[v]; sq = fmaf(pn[v], pn[v], sq); }
        s  += __shfl_down_sync(0xffffffffu, s,  2, 4);
        s  += __shfl_down_sync(0xffffffffu, s,  1, 4);
        sq += __shfl_down_sync(0xffffffffu, sq, 2, 4);
        sq += __shfl_down_sync(0xffffffffu, sq, 1, 4);
        s  = __shfl_sync(0xffffffffu, s,  0, 4);
        sq = __shfl_sync(0xffffffffu, sq, 0, 4);

        const float mu  = s * (1.f / 128.f);
        const float var = sq * (1.f / 128.f) - mu * mu;
        const float inv = rsqrtf(var + 1e-5f);

#pragma unroll
        for (int u = 0; u < 8; u++) {
            int d = q * 32 + 4 * u;
            float4 gv = *(const float4*)&gamma[d];
            float4 bv = *(const float4*)&beta[d];
            float4 o;
            o.x = (pn[4 * u + 0] - mu) * inv * gv.x + bv.x;
            o.y = (pn[4 * u + 1] - mu) * inv * gv.y + bv.y;
            o.z = (pn[4 * u + 2] - mu) * inv * gv.z + bv.z;
            o.w = (pn[4 * u + 3] - mu) * inv * gv.w + bv.w;
            *(float4*)&out[(size_t)pair * D + d] = o;
        }
    }
#undef F_LOAD
}
#undef FCS

// ---------------------------------------------------------------------------
extern "C" void kernel_launch(void* const* d_in, const int* in_sizes, int n_in,
                              void* d_out, int out_size) {
    const float* P     = (const float*)d_in[0];
    const float* mask  = (const float*)d_in[1];
    const float* Wl    = (const float*)d_in[2];
    const float* Wr    = (const float*)d_in[3];
    const float* Wo    = (const float*)d_in[4];
    const float* gamma = (const float*)d_in[5];
    const float* beta  = (const float*)d_in[6];
    float* out = (float*)d_out;

    cudaFuncSetAttribute(k_tri, cudaFuncAttributeMaxDynamicSharedMemorySize, T_SMEM);

    k_wt<<<64, 256>>>(Wo);
    k_proj<<<dim3(LL / 128, 2), 256>>>(P, mask, Wl, Wr);
    k_tri<<<dim3(L / 128, L / 128, H), 256, T_SMEM>>>();
    k_fin<<<LL / 64, 256>>>(P, mask, gamma, beta, out);
}

// round 16
// speedup vs baseline: 1.0580x; 1.0580x over previous
#include <cuda_runtime.h>
#include <cuda_fp16.h>
#include <cstdint>

#define L  384
#define D  128
#define H  128
#define LL (L * L)   // 147456

// Scratch — static device globals (no cudaMalloc allowed).
__device__ __half g_LhT[(size_t)H * LL];  // [h][i*L+k]  (fp16)
__device__ __half g_RhT[(size_t)H * LL];  // [h][j*L+k]  (fp16, j-major)
__device__ __half g_updT[(size_t)H * LL]; // [h][i*L+j]  (fp16)
__device__ __half g_Wo2h[D * H];          // [d][h] = fp16(W_out[d][h])

// ---------------------------------------------------------------------------
// helpers
// ---------------------------------------------------------------------------
__device__ __forceinline__ void mma16(float c[4], const unsigned a[4], const unsigned b[2]) {
    asm volatile(
        "mma.sync.aligned.m16n8k16.row.col.f32.f16.f16.f32 "
        "{%0,%1,%2,%3}, {%4,%5,%6,%7}, {%8,%9}, {%0,%1,%2,%3};"
        : "+f"(c[0]), "+f"(c[1]), "+f"(c[2]), "+f"(c[3])
        : "r"(a[0]), "r"(a[1]), "r"(a[2]), "r"(a[3]), "r"(b[0]), "r"(b[1]));
}

__device__ __forceinline__ void ldsm4h(unsigned r[4], const __half* p) {
    unsigned a = (unsigned)__cvta_generic_to_shared(p);
    asm volatile("ldmatrix.sync.aligned.m8n8.x4.shared.b16 {%0,%1,%2,%3}, [%4];"
                 : "=r"(r[0]), "=r"(r[1]), "=r"(r[2]), "=r"(r[3]) : "r"(a));
}
__device__ __forceinline__ void ldsm4t(unsigned r[4], const __half* p) {
    unsigned a = (unsigned)__cvta_generic_to_shared(p);
    asm volatile("ldmatrix.sync.aligned.m8n8.x4.trans.shared.b16 {%0,%1,%2,%3}, [%4];"
                 : "=r"(r[0]), "=r"(r[1]), "=r"(r[2]), "=r"(r[3]) : "r"(a));
}

__device__ __forceinline__ void cpa16(void* dst, const void* src) {
    unsigned sa = (unsigned)__cvta_generic_to_shared(dst);
    asm volatile("cp.async.cg.shared.global [%0], [%1], 16;" :: "r"(sa), "l"(src));
}
__device__ __forceinline__ void cpa_commit() { asm volatile("cp.async.commit_group;"); }
__device__ __forceinline__ void cpa_wait0()  { asm volatile("cp.async.wait_group 0;"); }
__device__ __forceinline__ void cpa_wait2()  { asm volatile("cp.async.wait_group 2;"); }

// ---------------------------------------------------------------------------
// Kernel 0: fp16-round W_out (native [d][h] order) -> g_Wo2h
// ---------------------------------------------------------------------------
__global__ __launch_bounds__(256) void k_wt(const float* __restrict__ Wo) {
    int idx = blockIdx.x * 256 + threadIdx.x;   // 16384
    g_Wo2h[idx] = __float2half_rn(Wo[idx]);
}

// ---------------------------------------------------------------------------
// Kernel 1: projection GEMM — fp16 mma + ldmatrix (round-12, committed).
// ---------------------------------------------------------------------------
#define PCS(n, m) smf[(n) * 132 + (m)]

__global__ __launch_bounds__(256) void k_proj(
    const float* __restrict__ P, const float* __restrict__ mask,
    const float* __restrict__ Wl, const float* __restrict__ Wr)
{
    __shared__ __align__(16) float smf[5120];   // 20,480 B (halves alias floats)
    __half* sm = (__half*)smf;
    float* mV = smf + 32 * 132 + 16;            // 128 mask vals (epilogue reuse)

    const int tid = threadIdx.x;
    const int wid = tid >> 5, lane = tid & 31;
    const int wm = wid & 3, wn = wid >> 2;
    const int group = lane >> 2, tid4 = lane & 3;
    const int bid = blockIdx.x;
    const bool isL = (blockIdx.y == 0);
    const float* __restrict__ W = isL ? Wl : Wr;

    int srcBase, srcStride, dmBase;
    if (isL) {
        srcBase = bid * 128;  srcStride = 1;  dmBase = bid * 128;
    } else {
        int j = bid / 3, k0p = (bid % 3) * 128;
        srcBase = k0p * L + j;  srcStride = L;  dmBase = j * L + k0p;
    }

    int aOff[2], bOff[4];
#pragma unroll
    for (int mt = 0; mt < 2; mt++)
        aOff[mt] = (wm * 32 + mt * 16 + (lane & 7) + 8 * ((lane >> 3) & 1)) * 40
                 + 8 * (lane >> 4);
#pragma unroll
    for (int p = 0; p < 4; p++)
        bOff[p] = 5120 + (wn * 64 + p * 16 + (lane & 7) + 8 * (lane >> 4)) * 40
                + 8 * ((lane >> 3) & 1);

    float acc[2][8][4];
#pragma unroll
    for (int mt = 0; mt < 2; mt++)
#pragma unroll
        for (int nt = 0; nt < 8; nt++)
#pragma unroll
            for (int v = 0; v < 4; v++) acc[mt][nt][v] = 0.f;

    const int mld = tid >> 3;          // 0..31 (+32p)
    const int kld = (tid & 7) * 4;     // 0..28

    float4 va[4], vb[4];
#define P_FETCH(k0)                                                                 \
    {                                                                               \
        _Pragma("unroll")                                                           \
        for (int p = 0; p < 4; p++) {                                               \
            int m = mld + p * 32;                                                   \
            va[p] = *(const float4*)&P[(size_t)(srcBase + (size_t)m * srcStride) * D + (k0) + kld]; \
            vb[p] = *(const float4*)&W[m * D + (k0) + kld];                         \
        }                                                                           \
    }
#define P_STORE()                                                                   \
    {                                                                               \
        _Pragma("unroll")                                                           \
        for (int p = 0; p < 4; p++) {                                               \
            int m = mld + p * 32;                                                   \
            __half2 a0 = __floats2half2_rn(va[p].x, va[p].y);                       \
            __half2 a1 = __floats2half2_rn(va[p].z, va[p].w);                       \
            __half2 b0 = __floats2half2_rn(vb[p].x, vb[p].y);                       \
            __half2 b1 = __floats2half2_rn(vb[p].z, vb[p].w);                       \
            *(unsigned*)&sm[m * 40 + kld]            = *(unsigned*)&a0;             \
            *(unsigned*)&sm[m * 40 + kld + 2]        = *(unsigned*)&a1;             \
            *(unsigned*)&sm[5120 + m * 40 + kld]     = *(unsigned*)&b0;             \
            *(unsigned*)&sm[5120 + m * 40 + kld + 2] = *(unsigned*)&b1;             \
        }                                                                           \
    }

    P_FETCH(0);

#pragma unroll 1
    for (int it = 0; it < 4; it++) {
        __syncthreads();
        P_STORE();
        __syncthreads();
        if (it < 3) P_FETCH((it + 1) * 32);
#pragma unroll
        for (int ks = 0; ks < 2; ks++) {
            const int k = ks * 16;
            unsigned a[2][4], b[4][4];
#pragma unroll
            for (int mt = 0; mt < 2; mt++)
                ldsm4h(a[mt], &sm[aOff[mt] + k]);
#pragma unroll
            for (int p = 0; p < 4; p++)
                ldsm4h(b[p], &sm[bOff[p] + k]);
#pragma unroll
            for (int mt = 0; mt < 2; mt++)
#pragma unroll
                for (int p = 0; p < 4; p++) {
                    mma16(acc[mt][2 * p],     a[mt], &b[p][0]);
                    mma16(acc[mt][2 * p + 1], a[mt], &b[p][2]);
                }
        }
    }
#undef P_FETCH
#undef P_STORE

    __syncthreads();
    if (tid < 128) mV[tid] = mask[dmBase + tid];
    __half* __restrict__ dst = isL ? g_LhT : g_RhT;

#pragma unroll 1
    for (int nc = 0; nc < 4; nc++) {
        __syncthreads();
        if (wn == (nc >> 1)) {
#pragma unroll
            for (int nt2 = 0; nt2 < 4; nt2++) {
                int nt = (nc & 1) * 4 + nt2;
                int cc = nt2 * 8 + 2 * tid4;
#pragma unroll
                for (int mt = 0; mt < 2; mt++) {
                    int r = wm * 32 + mt * 16 + group;
                    PCS(cc,     r)     = acc[mt][nt][0];
                    PCS(cc + 1, r)     = acc[mt][nt][1];
                    PCS(cc,     r + 8) = acc[mt][nt][2];
                    PCS(cc + 1, r + 8) = acc[mt][nt][3];
                }
            }
        }
        __syncthreads();
#pragma unroll
        for (int p = 0; p < 4; p++) {
            int nr = (tid >> 5) + p * 8;
            int m  = (tid & 31) * 4;
            __half2 h0 = __floats2half2_rn(PCS(nr, m + 0) * mV[m + 0],
                                           PCS(nr, m + 1) * mV[m + 1]);
            __half2 h1 = __floats2half2_rn(PCS(nr, m + 2) * mV[m + 2],
                                           PCS(nr, m + 3) * mV[m + 3]);
            uint2 u = make_uint2(*(unsigned*)&h0, *(unsigned*)&h1);
            *(uint2*)&dst[(size_t)(nc * 32 + nr) * LL + dmBase + m] = u;
        }
    }
#undef PCS
}

// ---------------------------------------------------------------------------
// Kernel 2: triangle einsum — fp16 mma + ldmatrix, BK=64, one-sync 2-stage
// (round-14, best measured). Dynamic smem 73,728 B.
// ---------------------------------------------------------------------------
#define T_STG 18432                   // halves per stage: A 128*72 + B 128*72
#define T_SMEM (2 * T_STG * 2)        // 73,728 B
#define TCS(m, j)    smf[(m) * 132 + (j)]

__global__ __launch_bounds__(256, 2) void k_tri() {
    extern __shared__ __align__(16) float smf[];
    __half* sm = (__half*)smf;

    const int tid = threadIdx.x;
    const int wid = tid >> 5, lane = tid & 31;
    const int wm = wid & 3, wn = wid >> 2;
    const int group = lane >> 2, tid4 = lane & 3;
    const size_t hoff = (size_t)blockIdx.z * LL;
    const int i0 = blockIdx.y * 128;
    const int j0 = blockIdx.x * 128;

    const __half* __restrict__ A = g_LhT + hoff;
    const __half* __restrict__ B = g_RhT + hoff;

    int aOff[2], bOff[4];
#pragma unroll
    for (int mt = 0; mt < 2; mt++)
        aOff[mt] = (wm * 32 + mt * 16 + (lane & 7) + 8 * ((lane >> 3) & 1)) * 72
                 + 8 * (lane >> 4);
#pragma unroll
    for (int p = 0; p < 4; p++)
        bOff[p] = 9216 + (wn * 64 + p * 16 + (lane & 7) + 8 * (lane >> 4)) * 72
                + 8 * ((lane >> 3) & 1);

    float acc[2][8][4];
#pragma unroll
    for (int mt = 0; mt < 2; mt++)
#pragma unroll
        for (int nt = 0; nt < 8; nt++)
#pragma unroll
            for (int v = 0; v < 4; v++) acc[mt][nt][v] = 0.f;

#define T_LOAD(s, k0)                                                              \
    {                                                                              \
        _Pragma("unroll")                                                          \
        for (int p = 0; p < 4; p++) {                                              \
            int task = tid + p * 256;                                              \
            int r = task >> 3, q = task & 7;                                       \
            cpa16(&sm[(s) * T_STG + r * 72 + q * 8],                               \
                  &A[(size_t)(i0 + r) * L + (k0) + q * 8]);                        \
            cpa16(&sm[(s) * T_STG + 9216 + r * 72 + q * 8],                        \
                  &B[(size_t)(j0 + r) * L + (k0) + q * 8]);                        \
        }                                                                          \
    }

    T_LOAD(0, 0);  cpa_commit();

#pragma unroll 1
    for (int it = 0; it < 6; it++) {
        const int s = it & 1;
        cpa_wait0();
        __syncthreads();
        if (it < 5) T_LOAD(s ^ 1, (it + 1) * 64);
        cpa_commit();
#pragma unroll
        for (int ks = 0; ks < 4; ks++) {
            const int k = ks * 16;
            unsigned a[2][4], b[4][4];
#pragma unroll
            for (int mt = 0; mt < 2; mt++)
                ldsm4h(a[mt], &sm[s * T_STG + aOff[mt] + k]);
#pragma unroll
            for (int p = 0; p < 4; p++)
                ldsm4h(b[p], &sm[s * T_STG + bOff[p] + k]);
#pragma unroll
            for (int mt = 0; mt < 2; mt++)
#pragma unroll
                for (int p = 0; p < 4; p++) {
                    mma16(acc[mt][2 * p],     a[mt], &b[p][0]);
                    mma16(acc[mt][2 * p + 1], a[mt], &b[p][2]);
                }
        }
    }
#undef T_LOAD

    // Epilogue: two 64-row chunks staged through smem, coalesced fp16 store.
#pragma unroll 1
    for (int mc = 0; mc < 2; mc++) {
        __syncthreads();
        if ((wm >> 1) == mc) {
#pragma unroll
            for (int nt = 0; nt < 8; nt++) {
                int cc = wn * 64 + nt * 8 + 2 * tid4;
#pragma unroll
                for (int mt = 0; mt < 2; mt++) {
                    int r = (wm & 1) * 32 + mt * 16 + group;
                    TCS(r,     cc)     = acc[mt][nt][0];
                    TCS(r,     cc + 1) = acc[mt][nt][1];
                    TCS(r + 8, cc)     = acc[mt][nt][2];
                    TCS(r + 8, cc + 1) = acc[mt][nt][3];
                }
            }
        }
        __syncthreads();
#pragma unroll
        for (int p = 0; p < 8; p++) {
            int row = (tid >> 5) + p * 8;
            int j   = (tid & 31) * 4;
            __half2 h0 = __floats2half2_rn(TCS(row, j + 0), TCS(row, j + 1));
            __half2 h1 = __floats2half2_rn(TCS(row, j + 2), TCS(row, j + 3));
            uint2 u = make_uint2(*(unsigned*)&h0, *(unsigned*)&h1);
            *(uint2*)&g_updT[hoff + (size_t)(i0 + mc * 64 + row) * L + j0 + j] = u;
        }
    }
#undef TCS
}

// ---------------------------------------------------------------------------
// Kernel 3: output projection (fp16 mma) + residual + mask + LN.
// Round-13 variant (best measured 84.4 us): 128 threads, 2x2 warp grid,
// 3-stage cp.async, wait_group 2, two syncs per iteration.
// ---------------------------------------------------------------------------
#define F_STG 4224                    // halves per stage: A 16*72 + B 128*24
#define FCS(m, d)    sm[(m) * 132 + (d)]

__global__ __launch_bounds__(128, 4) void k_fin(
    const float* __restrict__ P, const float* __restrict__ mask,
    const float* __restrict__ gamma, const float* __restrict__ beta,
    float* __restrict__ out)
{
    __shared__ __align__(16) float sm[8448];   // 33,792 B
    __half* smh = (__half*)sm;

    const int tid = threadIdx.x;
    const int wid = tid >> 5, lane = tid & 31;
    const int wm = wid & 1, wn = wid >> 1;
    const int group = lane >> 2, tid4 = lane & 3;
    const int pairBase = blockIdx.x * 64;

    int aOff[2], bOff[4];
#pragma unroll
    for (int mt = 0; mt < 2; mt++)
        aOff[mt] = ((lane & 7) + 8 * (lane >> 4)) * 72
                 + wm * 32 + mt * 16 + 8 * ((lane >> 3) & 1);
#pragma unroll
    for (int p = 0; p < 4; p++)
        bOff[p] = 1152 + (wn * 64 + p * 16 + (lane & 7) + 8 * (lane >> 4)) * 24
                + 8 * ((lane >> 3) & 1);

    float acc[2][8][4];
#pragma unroll
    for (int mt = 0; mt < 2; mt++)
#pragma unroll
        for (int nt = 0; nt < 8; nt++)
#pragma unroll
            for (int v = 0; v < 4; v++) acc[mt][nt][v] = 0.f;

#define F_LOAD(s, k0)                                                                \
    {                                                                                \
        {                                                                            \
            int k = tid >> 3, m8 = (tid & 7) * 8;                                    \
            cpa16(&smh[(s) * F_STG + k * 72 + m8],                                   \
                  &g_updT[(size_t)((k0) + k) * LL + pairBase + m8]);                 \
        }                                                                            \
        _Pragma("unroll")                                                            \
        for (int p = 0; p < 2; p++) {                                                \
            int task = tid + p * 128;                                                \
            int n = task >> 1, q = (task & 1) * 8;                                   \
            cpa16(&smh[(s) * F_STG + 1152 + n * 24 + q],                             \
                  &g_Wo2h[n * H + (k0) + q]);                                        \
        }                                                                            \
    }

    F_LOAD(0, 0);  cpa_commit();
    F_LOAD(1, 16); cpa_commit();
    F_LOAD(2, 32); cpa_commit();

#pragma unroll 1
    for (int it = 0; it < 8; it++) {
        const int s = it % 3;
        cpa_wait2();
        __syncthreads();
        unsigned a[2][4], b[4][4];
#pragma unroll
        for (int mt = 0; mt < 2; mt++)
            ldsm4t(a[mt], &smh[s * F_STG + aOff[mt]]);
#pragma unroll
        for (int p = 0; p < 4; p++)
            ldsm4h(b[p], &smh[s * F_STG + bOff[p]]);
#pragma unroll
        for (int mt = 0; mt < 2; mt++)
#pragma unroll
            for (int p = 0; p < 4; p++) {
                mma16(acc[mt][2 * p],     a[mt], &b[p][0]);
                mma16(acc[mt][2 * p + 1], a[mt], &b[p][2]);
            }
        __syncthreads();
        if (it + 3 < 8) F_LOAD(s, (it + 3) * 16);
        cpa_commit();
    }

    // Epilogue: stage whole 64x128 acc tile -> smem, then LayerNorm.
    __syncthreads();
#pragma unroll
    for (int nt = 0; nt < 8; nt++) {
        int cc = wn * 64 + nt * 8 + 2 * tid4;
#pragma unroll
        for (int mt = 0; mt < 2; mt++) {
            int r = wm * 32 + mt * 16 + group;
            FCS(r,     cc)     = acc[mt][nt][0];
            FCS(r,     cc + 1) = acc[mt][nt][1];
            FCS(r + 8, cc)     = acc[mt][nt][2];
            FCS(r + 8, cc + 1) = acc[mt][nt][3];
        }
    }
    __syncthreads();

#pragma unroll 1
    for (int h2 = 0; h2 < 2; h2++) {
        const int row = (tid >> 2) + h2 * 32;
        const int q   = tid & 3;
        const int pair = pairBase + row;
        const float mk = mask[pair];

        float pn[32];
        float s = 0.f, sq = 0.f;
#pragma unroll
        for (int u = 0; u < 8; u++) {
            float4 pv = *(const float4*)&P[(size_t)pair * D + q * 32 + 4 * u];
            pn[4 * u + 0] = pv.x + mk * FCS(row, q * 32 + 4 * u + 0);
            pn[4 * u + 1] = pv.y + mk * FCS(row, q * 32 + 4 * u + 1);
            pn[4 * u + 2] = pv.z + mk * FCS(row, q * 32 + 4 * u + 2);
            pn[4 * u + 3] = pv.w + mk * FCS(row, q * 32 + 4 * u + 3);
        }
#pragma unroll
        for (int v = 0; v < 32; v++) { s += pn[v]; sq = fmaf(pn[v], pn[v], sq); }
        s  += __shfl_down_sync(0xffffffffu, s,  2, 4);
        s  += __shfl_down_sync(0xffffffffu, s,  1, 4);
        sq += __shfl_down_sync(0xffffffffu, sq, 2, 4);
        sq += __shfl_down_sync(0xffffffffu, sq, 1, 4);
        s  = __shfl_sync(0xffffffffu, s,  0, 4);
        sq = __shfl_sync(0xffffffffu, sq, 0, 4);

        const float mu  = s * (1.f / 128.f);
        const float var = sq * (1.f / 128.f) - mu * mu;
        const float inv = rsqrtf(var + 1e-5f);

#pragma unroll
        for (int u = 0; u < 8; u++) {
            int d = q * 32 + 4 * u;
            float4 gv = *(const float4*)&gamma[d];
            float4 bv = *(const float4*)&beta[d];
            float4 o;
            o.x = (pn[4 * u + 0] - mu) * inv * gv.x + bv.x;
            o.y = (pn[4 * u + 1] - mu) * inv * gv.y + bv.y;
            o.z = (pn[4 * u + 2] - mu) * inv * gv.z + bv.z;
            o.w = (pn[4 * u + 3] - mu) * inv * gv.w + bv.w;
            *(float4*)&out[(size_t)pair * D + d] = o;
        }
    }
#undef F_LOAD
}
#undef FCS

// ---------------------------------------------------------------------------
extern "C" void kernel_launch(void* const* d_in, const int* in_sizes, int n_in,
                              void* d_out, int out_size) {
    const float* P     = (const float*)d_in[0];
    const float* mask  = (const float*)d_in[1];
    const float* Wl    = (const float*)d_in[2];
    const float* Wr    = (const float*)d_in[3];
    const float* Wo    = (const float*)d_in[4];
    const float* gamma = (const float*)d_in[5];
    const float* beta  = (const float*)d_in[6];
    float* out = (float*)d_out;

    cudaFuncSetAttribute(k_tri, cudaFuncAttributeMaxDynamicSharedMemorySize, T_SMEM);

    k_wt<<<64, 256>>>(Wo);
    k_proj<<<dim3(LL / 128, 2), 256>>>(P, mask, Wl, Wr);
    k_tri<<<dim3(L / 128, L / 128, H), 256, T_SMEM>>>();
    k_fin<<<LL / 64, 128>>>(P, mask, gamma, beta, out);
}

// round 17
// speedup vs baseline: 1.0626x; 1.0043x over previous
#include <cuda_runtime.h>
#include <cuda_fp16.h>
#include <cstdint>

#define L  384
#define D  128
#define H  128
#define LL (L * L)   // 147456

// Scratch — static device globals (no cudaMalloc allowed).
__device__ __half g_LhT[(size_t)H * LL];  // [h][i*L+k]  (fp16)
__device__ __half g_RhT[(size_t)H * LL];  // [h][j*L+k]  (fp16, j-major)
__device__ __half g_updT[(size_t)H * LL]; // [h][i*L+j]  (fp16)
__device__ __half g_Wo2h[D * H];          // [d][h] = fp16(W_out[d][h])

// ---------------------------------------------------------------------------
// helpers
// ---------------------------------------------------------------------------
__device__ __forceinline__ void mma16(float c[4], const unsigned a[4], const unsigned b[2]) {
    asm volatile(
        "mma.sync.aligned.m16n8k16.row.col.f32.f16.f16.f32 "
        "{%0,%1,%2,%3}, {%4,%5,%6,%7}, {%8,%9}, {%0,%1,%2,%3};"
        : "+f"(c[0]), "+f"(c[1]), "+f"(c[2]), "+f"(c[3])
        : "r"(a[0]), "r"(a[1]), "r"(a[2]), "r"(a[3]), "r"(b[0]), "r"(b[1]));
}

__device__ __forceinline__ void ldsm4h(unsigned r[4], const __half* p) {
    unsigned a = (unsigned)__cvta_generic_to_shared(p);
    asm volatile("ldmatrix.sync.aligned.m8n8.x4.shared.b16 {%0,%1,%2,%3}, [%4];"
                 : "=r"(r[0]), "=r"(r[1]), "=r"(r[2]), "=r"(r[3]) : "r"(a));
}
__device__ __forceinline__ void ldsm4t(unsigned r[4], const __half* p) {
    unsigned a = (unsigned)__cvta_generic_to_shared(p);
    asm volatile("ldmatrix.sync.aligned.m8n8.x4.trans.shared.b16 {%0,%1,%2,%3}, [%4];"
                 : "=r"(r[0]), "=r"(r[1]), "=r"(r[2]), "=r"(r[3]) : "r"(a));
}

__device__ __forceinline__ void cpa16(void* dst, const void* src) {
    unsigned sa = (unsigned)__cvta_generic_to_shared(dst);
    asm volatile("cp.async.cg.shared.global [%0], [%1], 16;" :: "r"(sa), "l"(src));
}
__device__ __forceinline__ void cpa_commit() { asm volatile("cp.async.commit_group;"); }
__device__ __forceinline__ void cpa_wait0()  { asm volatile("cp.async.wait_group 0;"); }
__device__ __forceinline__ void cpa_wait2()  { asm volatile("cp.async.wait_group 2;"); }

// ---------------------------------------------------------------------------
// Kernel 1: projection GEMM — fp16 mma + ldmatrix (round-12 structure).
// Also folds the W_out fp16 conversion (g_Wo2h) into the first 64 isL blocks;
// g_Wo2h is consumed only by k_fin (two launches later), so no ordering hazard.
// ---------------------------------------------------------------------------
#define PCS(n, m) smf[(n) * 132 + (m)]

__global__ __launch_bounds__(256) void k_proj(
    const float* __restrict__ P, const float* __restrict__ mask,
    const float* __restrict__ Wl, const float* __restrict__ Wr,
    const float* __restrict__ Wo)
{
    __shared__ __align__(16) float smf[5120];   // 20,480 B (halves alias floats)
    __half* sm = (__half*)smf;
    float* mV = smf + 32 * 132 + 16;            // 128 mask vals (epilogue reuse)

    const int tid = threadIdx.x;
    const int wid = tid >> 5, lane = tid & 31;
    const int wm = wid & 3, wn = wid >> 2;
    const int group = lane >> 2, tid4 = lane & 3;
    const int bid = blockIdx.x;
    const bool isL = (blockIdx.y == 0);
    const float* __restrict__ W = isL ? Wl : Wr;

    // folded k_wt: 64 blocks x 256 threads = 16384 elements
    if (isL && bid < 64)
        g_Wo2h[bid * 256 + tid] = __float2half_rn(Wo[bid * 256 + tid]);

    int srcBase, srcStride, dmBase;
    if (isL) {
        srcBase = bid * 128;  srcStride = 1;  dmBase = bid * 128;
    } else {
        int j = bid / 3, k0p = (bid % 3) * 128;
        srcBase = k0p * L + j;  srcStride = L;  dmBase = j * L + k0p;
    }

    int aOff[2], bOff[4];
#pragma unroll
    for (int mt = 0; mt < 2; mt++)
        aOff[mt] = (wm * 32 + mt * 16 + (lane & 7) + 8 * ((lane >> 3) & 1)) * 40
                 + 8 * (lane >> 4);
#pragma unroll
    for (int p = 0; p < 4; p++)
        bOff[p] = 5120 + (wn * 64 + p * 16 + (lane & 7) + 8 * (lane >> 4)) * 40
                + 8 * ((lane >> 3) & 1);

    float acc[2][8][4];
#pragma unroll
    for (int mt = 0; mt < 2; mt++)
#pragma unroll
        for (int nt = 0; nt < 8; nt++)
#pragma unroll
            for (int v = 0; v < 4; v++) acc[mt][nt][v] = 0.f;

    const int mld = tid >> 3;          // 0..31 (+32p)
    const int kld = (tid & 7) * 4;     // 0..28

    float4 va[4], vb[4];
#define P_FETCH(k0)                                                                 \
    {                                                                               \
        _Pragma("unroll")                                                           \
        for (int p = 0; p < 4; p++) {                                               \
            int m = mld + p * 32;                                                   \
            va[p] = *(const float4*)&P[(size_t)(srcBase + (size_t)m * srcStride) * D + (k0) + kld]; \
            vb[p] = *(const float4*)&W[m * D + (k0) + kld];                         \
        }                                                                           \
    }
#define P_STORE()                                                                   \
    {                                                                               \
        _Pragma("unroll")                                                           \
        for (int p = 0; p < 4; p++) {                                               \
            int m = mld + p * 32;                                                   \
            __half2 a0 = __floats2half2_rn(va[p].x, va[p].y);                       \
            __half2 a1 = __floats2half2_rn(va[p].z, va[p].w);                       \
            __half2 b0 = __floats2half2_rn(vb[p].x, vb[p].y);                       \
            __half2 b1 = __floats2half2_rn(vb[p].z, vb[p].w);                       \
            *(unsigned*)&sm[m * 40 + kld]            = *(unsigned*)&a0;             \
            *(unsigned*)&sm[m * 40 + kld + 2]        = *(unsigned*)&a1;             \
            *(unsigned*)&sm[5120 + m * 40 + kld]     = *(unsigned*)&b0;             \
            *(unsigned*)&sm[5120 + m * 40 + kld + 2] = *(unsigned*)&b1;             \
        }                                                                           \
    }

    P_FETCH(0);

#pragma unroll 1
    for (int it = 0; it < 4; it++) {
        __syncthreads();
        P_STORE();
        __syncthreads();
        if (it < 3) P_FETCH((it + 1) * 32);
#pragma unroll
        for (int ks = 0; ks < 2; ks++) {
            const int k = ks * 16;
            unsigned a[2][4], b[4][4];
#pragma unroll
            for (int mt = 0; mt < 2; mt++)
                ldsm4h(a[mt], &sm[aOff[mt] + k]);
#pragma unroll
            for (int p = 0; p < 4; p++)
                ldsm4h(b[p], &sm[bOff[p] + k]);
#pragma unroll
            for (int mt = 0; mt < 2; mt++)
#pragma unroll
                for (int p = 0; p < 4; p++) {
                    mma16(acc[mt][2 * p],     a[mt], &b[p][0]);
                    mma16(acc[mt][2 * p + 1], a[mt], &b[p][2]);
                }
        }
    }
#undef P_FETCH
#undef P_STORE

    __syncthreads();
    if (tid < 128) mV[tid] = mask[dmBase + tid];
    __half* __restrict__ dst = isL ? g_LhT : g_RhT;

#pragma unroll 1
    for (int nc = 0; nc < 4; nc++) {
        __syncthreads();
        if (wn == (nc >> 1)) {
#pragma unroll
            for (int nt2 = 0; nt2 < 4; nt2++) {
                int nt = (nc & 1) * 4 + nt2;
                int cc = nt2 * 8 + 2 * tid4;
#pragma unroll
                for (int mt = 0; mt < 2; mt++) {
                    int r = wm * 32 + mt * 16 + group;
                    PCS(cc,     r)     = acc[mt][nt][0];
                    PCS(cc + 1, r)     = acc[mt][nt][1];
                    PCS(cc,     r + 8) = acc[mt][nt][2];
                    PCS(cc + 1, r + 8) = acc[mt][nt][3];
                }
            }
        }
        __syncthreads();
#pragma unroll
        for (int p = 0; p < 4; p++) {
            int nr = (tid >> 5) + p * 8;
            int m  = (tid & 31) * 4;
            __half2 h0 = __floats2half2_rn(PCS(nr, m + 0) * mV[m + 0],
                                           PCS(nr, m + 1) * mV[m + 1]);
            __half2 h1 = __floats2half2_rn(PCS(nr, m + 2) * mV[m + 2],
                                           PCS(nr, m + 3) * mV[m + 3]);
            uint2 u = make_uint2(*(unsigned*)&h0, *(unsigned*)&h1);
            *(uint2*)&dst[(size_t)(nc * 32 + nr) * LL + dmBase + m] = u;
        }
    }
#undef PCS
}

// ---------------------------------------------------------------------------
// Kernel 2: triangle einsum — fp16 mma + ldmatrix, BK=64, one-sync 2-stage
// (round-14, best measured). Dynamic smem 73,728 B.
// ---------------------------------------------------------------------------
#define T_STG 18432                   // halves per stage: A 128*72 + B 128*72
#define T_SMEM (2 * T_STG * 2)        // 73,728 B
#define TCS(m, j)    smf[(m) * 132 + (j)]

__global__ __launch_bounds__(256, 2) void k_tri() {
    extern __shared__ __align__(16) float smf[];
    __half* sm = (__half*)smf;

    const int tid = threadIdx.x;
    const int wid = tid >> 5, lane = tid & 31;
    const int wm = wid & 3, wn = wid >> 2;
    const int group = lane >> 2, tid4 = lane & 3;
    const size_t hoff = (size_t)blockIdx.z * LL;
    const int i0 = blockIdx.y * 128;
    const int j0 = blockIdx.x * 128;

    const __half* __restrict__ A = g_LhT + hoff;
    const __half* __restrict__ B = g_RhT + hoff;

    int aOff[2], bOff[4];
#pragma unroll
    for (int mt = 0; mt < 2; mt++)
        aOff[mt] = (wm * 32 + mt * 16 + (lane & 7) + 8 * ((lane >> 3) & 1)) * 72
                 + 8 * (lane >> 4);
#pragma unroll
    for (int p = 0; p < 4; p++)
        bOff[p] = 9216 + (wn * 64 + p * 16 + (lane & 7) + 8 * (lane >> 4)) * 72
                + 8 * ((lane >> 3) & 1);

    float acc[2][8][4];
#pragma unroll
    for (int mt = 0; mt < 2; mt++)
#pragma unroll
        for (int nt = 0; nt < 8; nt++)
#pragma unroll
            for (int v = 0; v < 4; v++) acc[mt][nt][v] = 0.f;

#define T_LOAD(s, k0)                                                              \
    {                                                                              \
        _Pragma("unroll")                                                          \
        for (int p = 0; p < 4; p++) {                                              \
            int task = tid + p * 256;                                              \
            int r = task >> 3, q = task & 7;                                       \
            cpa16(&sm[(s) * T_STG + r * 72 + q * 8],                               \
                  &A[(size_t)(i0 + r) * L + (k0) + q * 8]);                        \
            cpa16(&sm[(s) * T_STG + 9216 + r * 72 + q * 8],                        \
                  &B[(size_t)(j0 + r) * L + (k0) + q * 8]);                        \
        }                                                                          \
    }

    T_LOAD(0, 0);  cpa_commit();

#pragma unroll 1
    for (int it = 0; it < 6; it++) {
        const int s = it & 1;
        cpa_wait0();
        __syncthreads();
        if (it < 5) T_LOAD(s ^ 1, (it + 1) * 64);
        cpa_commit();
#pragma unroll
        for (int ks = 0; ks < 4; ks++) {
            const int k = ks * 16;
            unsigned a[2][4], b[4][4];
#pragma unroll
            for (int mt = 0; mt < 2; mt++)
                ldsm4h(a[mt], &sm[s * T_STG + aOff[mt] + k]);
#pragma unroll
            for (int p = 0; p < 4; p++)
                ldsm4h(b[p], &sm[s * T_STG + bOff[p] + k]);
#pragma unroll
            for (int mt = 0; mt < 2; mt++)
#pragma unroll
                for (int p = 0; p < 4; p++) {
                    mma16(acc[mt][2 * p],     a[mt], &b[p][0]);
                    mma16(acc[mt][2 * p + 1], a[mt], &b[p][2]);
                }
        }
    }
#undef T_LOAD

    // Epilogue: two 64-row chunks staged through smem, coalesced fp16 store.
#pragma unroll 1
    for (int mc = 0; mc < 2; mc++) {
        __syncthreads();
        if ((wm >> 1) == mc) {
#pragma unroll
            for (int nt = 0; nt < 8; nt++) {
                int cc = wn * 64 + nt * 8 + 2 * tid4;
#pragma unroll
                for (int mt = 0; mt < 2; mt++) {
                    int r = (wm & 1) * 32 + mt * 16 + group;
                    TCS(r,     cc)     = acc[mt][nt][0];
                    TCS(r,     cc + 1) = acc[mt][nt][1];
                    TCS(r + 8, cc)     = acc[mt][nt][2];
                    TCS(r + 8, cc + 1) = acc[mt][nt][3];
                }
            }
        }
        __syncthreads();
#pragma unroll
        for (int p = 0; p < 8; p++) {
            int row = (tid >> 5) + p * 8;
            int j   = (tid & 31) * 4;
            __half2 h0 = __floats2half2_rn(TCS(row, j + 0), TCS(row, j + 1));
            __half2 h1 = __floats2half2_rn(TCS(row, j + 2), TCS(row, j + 3));
            uint2 u = make_uint2(*(unsigned*)&h0, *(unsigned*)&h1);
            *(uint2*)&g_updT[hoff + (size_t)(i0 + mc * 64 + row) * L + j0 + j] = u;
        }
    }
#undef TCS
}

// ---------------------------------------------------------------------------
// Kernel 3: output projection (fp16 mma) + residual + mask + LN.
// Round-13 variant (best measured): 128 threads, 2x2 warp grid, 3-stage
// cp.async, wait_group 2, two syncs per iteration.
// ---------------------------------------------------------------------------
#define F_STG 4224                    // halves per stage: A 16*72 + B 128*24
#define FCS(m, d)    sm[(m) * 132 + (d)]

__global__ __launch_bounds__(128, 4) void k_fin(
    const float* __restrict__ P, const float* __restrict__ mask,
    const float* __restrict__ gamma, const float* __restrict__ beta,
    float* __restrict__ out)
{
    __shared__ __align__(16) float sm[8448];   // 33,792 B
    __half* smh = (__half*)sm;

    const int tid = threadIdx.x;
    const int wid = tid >> 5, lane = tid & 31;
    const int wm = wid & 1, wn = wid >> 1;
    const int group = lane >> 2, tid4 = lane & 3;
    const int pairBase = blockIdx.x * 64;

    int aOff[2], bOff[4];
#pragma unroll
    for (int mt = 0; mt < 2; mt++)
        aOff[mt] = ((lane & 7) + 8 * (lane >> 4)) * 72
                 + wm * 32 + mt * 16 + 8 * ((lane >> 3) & 1);
#pragma unroll
    for (int p = 0; p < 4; p++)
        bOff[p] = 1152 + (wn * 64 + p * 16 + (lane & 7) + 8 * (lane >> 4)) * 24
                + 8 * ((lane >> 3) & 1);

    float acc[2][8][4];
#pragma unroll
    for (int mt = 0; mt < 2; mt++)
#pragma unroll
        for (int nt = 0; nt < 8; nt++)
#pragma unroll
            for (int v = 0; v < 4; v++) acc[mt][nt][v] = 0.f;

#define F_LOAD(s, k0)                                                                \
    {                                                                                \
        {                                                                            \
            int k = tid >> 3, m8 = (tid & 7) * 8;                                    \
            cpa16(&smh[(s) * F_STG + k * 72 + m8],                                   \
                  &g_updT[(size_t)((k0) + k) * LL + pairBase + m8]);                 \
        }                                                                            \
        _Pragma("unroll")                                                            \
        for (int p = 0; p < 2; p++) {                                                \
            int task = tid + p * 128;                                                \
            int n = task >> 1, q = (task & 1) * 8;                                   \
            cpa16(&smh[(s) * F_STG + 1152 + n * 24 + q],                             \
                  &g_Wo2h[n * H + (k0) + q]);                                        \
        }                                                                            \
    }

    F_LOAD(0, 0);  cpa_commit();
    F_LOAD(1, 16); cpa_commit();
    F_LOAD(2, 32); cpa_commit();

#pragma unroll 1
    for (int it = 0; it < 8; it++) {
        const int s = it % 3;
        cpa_wait2();
        __syncthreads();
        unsigned a[2][4], b[4][4];
#pragma unroll
        for (int mt = 0; mt < 2; mt++)
            ldsm4t(a[mt], &smh[s * F_STG + aOff[mt]]);
#pragma unroll
        for (int p = 0; p < 4; p++)
            ldsm4h(b[p], &smh[s * F_STG + bOff[p]]);
#pragma unroll
        for (int mt = 0; mt < 2; mt++)
#pragma unroll
            for (int p = 0; p < 4; p++) {
                mma16(acc[mt][2 * p],     a[mt], &b[p][0]);
                mma16(acc[mt][2 * p + 1], a[mt], &b[p][2]);
            }
        __syncthreads();
        if (it + 3 < 8) F_LOAD(s, (it + 3) * 16);
        cpa_commit();
    }

    // Epilogue: stage whole 64x128 acc tile -> smem, then LayerNorm.
    __syncthreads();
#pragma unroll
    for (int nt = 0; nt < 8; nt++) {
        int cc = wn * 64 + nt * 8 + 2 * tid4;
#pragma unroll
        for (int mt = 0; mt < 2; mt++) {
            int r = wm * 32 + mt * 16 + group;
            FCS(r,     cc)     = acc[mt][nt][0];
            FCS(r,     cc + 1) = acc[mt][nt][1];
            FCS(r + 8, cc)     = acc[mt][nt][2];
            FCS(r + 8, cc + 1) = acc[mt][nt][3];
        }
    }
    __syncthreads();

#pragma unroll 1
    for (int h2 = 0; h2 < 2; h2++) {
        const int row = (tid >> 2) + h2 * 32;
        const int q   = tid & 3;
        const int pair = pairBase + row;
        const float mk = mask[pair];

        float pn[32];
        float s = 0.f, sq = 0.f;
#pragma unroll
        for (int u = 0; u < 8; u++) {
            float4 pv = *(const float4*)&P[(size_t)pair * D + q * 32 + 4 * u];
            pn[4 * u + 0] = pv.x + mk * FCS(row, q * 32 + 4 * u + 0);
            pn[4 * u + 1] = pv.y + mk * FCS(row, q * 32 + 4 * u + 1);
            pn[4 * u + 2] = pv.z + mk * FCS(row, q * 32 + 4 * u + 2);
            pn[4 * u + 3] = pv.w + mk * FCS(row, q * 32 + 4 * u + 3);
        }
#pragma unroll
        for (int v = 0; v < 32; v++) { s += pn[v]; sq = fmaf(pn[v], pn[v], sq); }
        s  += __shfl_down_sync(0xffffffffu, s,  2, 4);
        s  += __shfl_down_sync(0xffffffffu, s,  1, 4);
        sq += __shfl_down_sync(0xffffffffu, sq, 2, 4);
        sq += __shfl_down_sync(0xffffffffu, sq, 1, 4);
        s  = __shfl_sync(0xffffffffu, s,  0, 4);
        sq = __shfl_sync(0xffffffffu, sq, 0, 4);

        const float mu  = s * (1.f / 128.f);
        const float var = sq * (1.f / 128.f) - mu * mu;
        const float inv = rsqrtf(var + 1e-5f);

#pragma unroll
        for (int u = 0; u < 8; u++) {
            int d = q * 32 + 4 * u;
            float4 gv = *(const float4*)&gamma[d];
            float4 bv = *(const float4*)&beta[d];
            float4 o;
            o.x = (pn[4 * u + 0] - mu) * inv * gv.x + bv.x;
            o.y = (pn[4 * u + 1] - mu) * inv * gv.y + bv.y;
            o.z = (pn[4 * u + 2] - mu) * inv * gv.z + bv.z;
            o.w = (pn[4 * u + 3] - mu) * inv * gv.w + bv.w;
            *(float4*)&out[(size_t)pair * D + d] = o;
        }
    }
#undef F_LOAD
}
#undef FCS

// ---------------------------------------------------------------------------
extern "C" void kernel_launch(void* const* d_in, const int* in_sizes, int n_in,
                              void* d_out, int out_size) {
    const float* P     = (const float*)d_in[0];
    const float* mask  = (const float*)d_in[1];
    const float* Wl    = (const float*)d_in[2];
    const float* Wr    = (const float*)d_in[3];
    const float* Wo    = (const float*)d_in[4];
    const float* gamma = (const float*)d_in[5];
    const float* beta  = (const float*)d_in[6];
    float* out = (float*)d_out;

    cudaFuncSetAttribute(k_tri, cudaFuncAttributeMaxDynamicSharedMemorySize, T_SMEM);

    k_proj<<<dim3(LL / 128, 2), 256>>>(P, mask, Wl, Wr, Wo);
    k_tri<<<dim3(L / 128, L / 128, H), 256, T_SMEM>>>();
    k_fin<<<LL / 64, 128>>>(P, mask, gamma, beta, out);
}